// round 1
// baseline (speedup 1.0000x reference)
#include <cuda_runtime.h>

#define NN 100000
#define NE 400000
#define NG 4096
#define DD 128
#define HH 256
#define NL 20
#define G_EPS 1e-7f
#define BNEPS 1e-5f

// ---------------- scratch (static device memory; no allocation) ----------------
__device__ float g_hA[(size_t)NN * DD];
__device__ float g_hB[(size_t)NN * DD];
__device__ float g_hh[(size_t)NN * DD];
__device__ float g_y1[(size_t)NN * HH];
__device__ float g_y2[(size_t)NN * HH];
__device__ int   g_deg[NN];
__device__ int   g_rowptr[NN + 1];
__device__ int   g_cursor[NN];
__device__ int   g_eids[NE];
__device__ float g_st1S[HH], g_st1Q[HH];
__device__ float g_st2S[HH], g_st2Q[HH];
__device__ float g_stHS[DD], g_stHQ[DD];
__device__ float g_bnAh[DD], g_bnBh[DD];
__device__ float g_bnA1[HH], g_bnB1[HH];
__device__ float g_bnA2[HH], g_bnB2[HH];
__device__ float g_hg[(size_t)NG * DD];
__device__ float g_cnt[NG];

// ---------------- atom encoder: h[n,c] = sum_i emb[i, x[n,i], c] ----------------
__global__ void atom_kernel(const int* __restrict__ x, const float* __restrict__ emb,
                            float* __restrict__ h) {
    int n = blockIdx.x, c = threadIdx.x;
    __shared__ int xi[9];
    if (c < 9) xi[c] = x[n * 9 + c];
    __syncthreads();
    float s = 0.f;
#pragma unroll
    for (int i = 0; i < 9; i++) s += emb[((size_t)i * 119 + xi[i]) * DD + c];
    h[(size_t)n * DD + c] = s;
}

// ---------------- CSR build ----------------
__global__ void hist_kernel(const int* __restrict__ dst, int* __restrict__ deg) {
    int e = blockIdx.x * blockDim.x + threadIdx.x;
    if (e < NE) atomicAdd(&deg[dst[e]], 1);
}

__global__ void scan_kernel(const int* __restrict__ deg, int* __restrict__ rowptr,
                            int* __restrict__ cursor) {
    __shared__ int sums[1024];
    int tid = threadIdx.x;
    const int CH = (NN + 1023) / 1024;
    int start = tid * CH;
    int s = 0;
    for (int i = 0; i < CH; i++) {
        int idx = start + i;
        if (idx < NN) s += deg[idx];
    }
    sums[tid] = s;
    __syncthreads();
    for (int off = 1; off < 1024; off <<= 1) {
        int v = (tid >= off) ? sums[tid - off] : 0;
        __syncthreads();
        sums[tid] += v;
        __syncthreads();
    }
    int run = (tid == 0) ? 0 : sums[tid - 1];
    for (int i = 0; i < CH; i++) {
        int idx = start + i;
        if (idx < NN) {
            rowptr[idx] = run;
            cursor[idx] = run;
            run += deg[idx];
        }
    }
    if (tid == 1023) rowptr[NN] = sums[1023];
}

__global__ void scatter_kernel(const int* __restrict__ dst, int* __restrict__ cursor,
                               int* __restrict__ eids) {
    int e = blockIdx.x * blockDim.x + threadIdx.x;
    if (e < NE) {
        int pos = atomicAdd(&cursor[dst[e]], 1);
        eids[pos] = e;
    }
}

// ---------------- GENConv aggregation: one warp per node, online softmax ----------------
__global__ __launch_bounds__(256) void agg_kernel(
    const float* __restrict__ h, const float* __restrict__ bnA, const float* __restrict__ bnB,
    const int* __restrict__ src, const int* __restrict__ eattr,
    const int* __restrict__ rowptr, const int* __restrict__ eids,
    const float* __restrict__ bond, const float* __restrict__ tptr, int layer,
    float* __restrict__ hh) {
    __shared__ float sb[3 * 6 * DD];
    int tid = threadIdx.x;
    for (int i = tid; i < 3 * 6 * DD; i += blockDim.x) sb[i] = bond[i];
    __syncthreads();
    float t = __ldg(&tptr[layer]);
    int warp = blockIdx.x * (blockDim.x >> 5) + (tid >> 5);
    if (warp >= NN) return;
    int lane = tid & 31;
    bool hasBn = (bnA != nullptr);

    float A[4], B[4], h2n[4];
#pragma unroll
    for (int u = 0; u < 4; u++) {
        int c = lane + 32 * u;
        float a = hasBn ? bnA[c] : 1.f;
        float b = hasBn ? bnB[c] : 0.f;
        A[u] = a; B[u] = b;
        float v = h[(size_t)warp * DD + c];
        if (hasBn) v = fmaxf(v * a + b, 0.f);
        h2n[u] = v;
    }
    const float NEGINF = __int_as_float(0xff800000);
    float m[4] = {NEGINF, NEGINF, NEGINF, NEGINF};
    float s1[4] = {0.f, 0.f, 0.f, 0.f};
    float s2[4] = {0.f, 0.f, 0.f, 0.f};
    int e0 = rowptr[warp], e1 = rowptr[warp + 1];
    for (int e = e0; e < e1; e++) {
        int eid = eids[e];
        int s = src[eid];
        int a0 = eattr[eid * 3 + 0];
        int a1 = eattr[eid * 3 + 1];
        int a2 = eattr[eid * 3 + 2];
        const float* hs = h + (size_t)s * DD;
#pragma unroll
        for (int u = 0; u < 4; u++) {
            int c = lane + 32 * u;
            float hv = hs[c];
            if (hasBn) hv = fmaxf(hv * A[u] + B[u], 0.f);
            float ee = sb[a0 * DD + c] + sb[(6 + a1) * DD + c] + sb[(12 + a2) * DD + c];
            float msg = fmaxf(hv + ee, 0.f) + G_EPS;
            float sc = msg * t;
            if (sc > m[u]) {
                float r = __expf(m[u] - sc);
                s1[u] = s1[u] * r + 1.f;
                s2[u] = s2[u] * r + msg;
                m[u] = sc;
            } else {
                float ex = __expf(sc - m[u]);
                s1[u] += ex;
                s2[u] += msg * ex;
            }
        }
    }
#pragma unroll
    for (int u = 0; u < 4; u++) {
        float mm = s2[u] / fmaxf(s1[u], G_EPS);
        hh[(size_t)warp * DD + lane + 32 * u] = h2n[u] + mm;
    }
}

// ---------------- fp32 tiled GEMM: C = f(A) @ W + bias (+res), col stats fused ----------------
// f(a) = trA ? relu(a*trA[k]+trB[k]) : a. Tile 128x64, BK=16, 256 thr, 8x4 per thread.
__global__ __launch_bounds__(256, 2) void gemm_kernel(
    const float* __restrict__ A, const float* __restrict__ W, const float* __restrict__ bias,
    const float* __restrict__ trA, const float* __restrict__ trB,
    const float* __restrict__ res, float* __restrict__ C,
    float* __restrict__ statS, float* __restrict__ statQ, int K, int Ncols) {
    __shared__ float As[16 * 132];
    __shared__ float Bs[16 * 64];
    int t = threadIdx.x;
    int tx = t & 15, ty = t >> 4;
    int arow = t >> 1, acol = (t & 1) * 8;
    int brow = t >> 4, bcol = (t & 15) * 4;
    int gr = blockIdx.y * 128 + arow;
    int gc0 = blockIdx.x * 64;
    float acc[8][4];
#pragma unroll
    for (int i = 0; i < 8; i++)
#pragma unroll
        for (int j = 0; j < 4; j++) acc[i][j] = 0.f;
    const float* Abase = A + (size_t)gr * K;
    bool hasTr = (trA != nullptr);

    for (int k0 = 0; k0 < K; k0 += 16) {
        float av[8];
        if (gr < NN) {
            float4 v0 = *(const float4*)(Abase + k0 + acol);
            float4 v1 = *(const float4*)(Abase + k0 + acol + 4);
            av[0] = v0.x; av[1] = v0.y; av[2] = v0.z; av[3] = v0.w;
            av[4] = v1.x; av[5] = v1.y; av[6] = v1.z; av[7] = v1.w;
        } else {
#pragma unroll
            for (int j = 0; j < 8; j++) av[j] = 0.f;
        }
        if (hasTr) {
#pragma unroll
            for (int j = 0; j < 8; j++) {
                int kg = k0 + acol + j;
                av[j] = fmaxf(av[j] * __ldg(&trA[kg]) + __ldg(&trB[kg]), 0.f);
            }
        }
#pragma unroll
        for (int j = 0; j < 8; j++) As[(acol + j) * 132 + arow] = av[j];
        float4 wv = *(const float4*)(W + (size_t)(k0 + brow) * Ncols + gc0 + bcol);
        *(float4*)&Bs[brow * 64 + bcol] = wv;
        __syncthreads();
#pragma unroll
        for (int k = 0; k < 16; k++) {
            float4 a0 = *(const float4*)&As[k * 132 + ty * 8];
            float4 a1 = *(const float4*)&As[k * 132 + ty * 8 + 4];
            float4 b  = *(const float4*)&Bs[k * 64 + tx * 4];
            float ar[8] = {a0.x, a0.y, a0.z, a0.w, a1.x, a1.y, a1.z, a1.w};
            float br[4] = {b.x, b.y, b.z, b.w};
#pragma unroll
            for (int i = 0; i < 8; i++)
#pragma unroll
                for (int j = 0; j < 4; j++) acc[i][j] += ar[i] * br[j];
        }
        __syncthreads();
    }
    // epilogue
    int r0 = blockIdx.y * 128 + ty * 8;
    int c0 = gc0 + tx * 4;
    float4 bb = *(const float4*)(bias + c0);
    float bsum[4] = {0.f, 0.f, 0.f, 0.f}, bsq[4] = {0.f, 0.f, 0.f, 0.f};
    bool doStat = (statS != nullptr);
#pragma unroll
    for (int i = 0; i < 8; i++) {
        int r = r0 + i;
        if (r < NN) {
            float4 v;
            v.x = acc[i][0] + bb.x; v.y = acc[i][1] + bb.y;
            v.z = acc[i][2] + bb.z; v.w = acc[i][3] + bb.w;
            if (res) {
                float4 rv = *(const float4*)(res + (size_t)r * Ncols + c0);
                v.x += rv.x; v.y += rv.y; v.z += rv.z; v.w += rv.w;
            }
            *(float4*)(C + (size_t)r * Ncols + c0) = v;
            if (doStat) {
                bsum[0] += v.x; bsq[0] += v.x * v.x;
                bsum[1] += v.y; bsq[1] += v.y * v.y;
                bsum[2] += v.z; bsq[2] += v.z * v.z;
                bsum[3] += v.w; bsq[3] += v.w * v.w;
            }
        }
    }
    if (doStat) {
        __syncthreads();
        float* sS = As;  // reuse (2112 >= 1024 floats)
        float* sQ = Bs;  // reuse (1024 floats)
#pragma unroll
        for (int j = 0; j < 4; j++) {
            sS[ty * 64 + tx * 4 + j] = bsum[j];
            sQ[ty * 64 + tx * 4 + j] = bsq[j];
        }
        __syncthreads();
        if (t < 64) {
            float s = 0.f, q = 0.f;
#pragma unroll
            for (int r2 = 0; r2 < 16; r2++) { s += sS[r2 * 64 + t]; q += sQ[r2 * 64 + t]; }
            atomicAdd(&statS[gc0 + t], s);
            atomicAdd(&statQ[gc0 + t], q);
        }
    }
}

// ---------------- BN stat finalize (+ zero next-stage stat buffers) ----------------
__global__ void finalize_kernel(const float* __restrict__ sum, const float* __restrict__ sq,
                                const float* __restrict__ g, const float* __restrict__ be,
                                float* __restrict__ outA, float* __restrict__ outB, int C,
                                float* __restrict__ z1, float* __restrict__ z2, int zlen) {
    int i = threadIdx.x;
    if (sum != nullptr && i < C) {
        float mu = sum[i] * (1.f / NN);
        float var = sq[i] * (1.f / NN) - mu * mu;
        float inv = rsqrtf(var + BNEPS);
        float a = g[i] * inv;
        outA[i] = a;
        outB[i] = be[i] - mu * a;
    }
    if (z1 != nullptr) {
        for (int j = i; j < zlen; j += blockDim.x) { z1[j] = 0.f; z2[j] = 0.f; }
    }
}

// ---------------- final BN + graph mean pool ----------------
__global__ void pool_kernel(const float* __restrict__ h, const float* __restrict__ bnA,
                            const float* __restrict__ bnB, const int* __restrict__ batch,
                            float* __restrict__ hg, float* __restrict__ cnt) {
    int n = blockIdx.x, c = threadIdx.x;
    int b = batch[n];
    float v = h[(size_t)n * DD + c] * bnA[c] + bnB[c];
    atomicAdd(&hg[(size_t)b * DD + c], v);
    if (c == 0) atomicAdd(&cnt[b], 1.f);
}

__global__ void out_kernel(const float* __restrict__ hg, const float* __restrict__ cnt,
                           const float* __restrict__ predW, const float* __restrict__ predb,
                           float* __restrict__ out) {
    int g = blockIdx.x, c = threadIdx.x;
    float scale = 1.f / fmaxf(cnt[g], 1.f);
    float v = hg[(size_t)g * DD + c] * scale * predW[c];
#pragma unroll
    for (int off = 16; off; off >>= 1) v += __shfl_down_sync(0xffffffffu, v, off);
    __shared__ float ws[4];
    if ((c & 31) == 0) ws[c >> 5] = v;
    __syncthreads();
    if (c == 0) out[g] = ws[0] + ws[1] + ws[2] + ws[3] + predb[0];
}

// ---------------- host orchestration ----------------
extern "C" void kernel_launch(void* const* d_in, const int* in_sizes, int n_in,
                              void* d_out, int out_size) {
    const int*   x        = (const int*)d_in[0];
    const int*   eidx     = (const int*)d_in[1];
    const int*   eattr    = (const int*)d_in[2];
    const int*   batch    = (const int*)d_in[3];
    const float* atom_emb = (const float*)d_in[4];
    const float* bond_emb = (const float*)d_in[5];
    const float* W1 = (const float*)d_in[6];
    const float* b1 = (const float*)d_in[7];
    const float* g1 = (const float*)d_in[8];
    const float* be1 = (const float*)d_in[9];
    const float* W2 = (const float*)d_in[10];
    const float* b2 = (const float*)d_in[11];
    const float* g2 = (const float*)d_in[12];
    const float* be2 = (const float*)d_in[13];
    const float* W3 = (const float*)d_in[14];
    const float* b3 = (const float*)d_in[15];
    const float* tt = (const float*)d_in[16];
    const float* norm_g = (const float*)d_in[17];
    const float* norm_b = (const float*)d_in[18];
    const float* predW = (const float*)d_in[19];
    const float* predb = (const float*)d_in[20];
    float* out = (float*)d_out;

    const int* src = eidx;
    const int* dst = eidx + NE;

    float *hA, *hB, *hh, *y1, *y2;
    int *deg, *rowptr, *cursor, *eids;
    float *st1S, *st1Q, *st2S, *st2Q, *stHS, *stHQ;
    float *bnAh, *bnBh, *bnA1, *bnB1, *bnA2, *bnB2;
    float *hg, *cnt;
    cudaGetSymbolAddress((void**)&hA, g_hA);
    cudaGetSymbolAddress((void**)&hB, g_hB);
    cudaGetSymbolAddress((void**)&hh, g_hh);
    cudaGetSymbolAddress((void**)&y1, g_y1);
    cudaGetSymbolAddress((void**)&y2, g_y2);
    cudaGetSymbolAddress((void**)&deg, g_deg);
    cudaGetSymbolAddress((void**)&rowptr, g_rowptr);
    cudaGetSymbolAddress((void**)&cursor, g_cursor);
    cudaGetSymbolAddress((void**)&eids, g_eids);
    cudaGetSymbolAddress((void**)&st1S, g_st1S);
    cudaGetSymbolAddress((void**)&st1Q, g_st1Q);
    cudaGetSymbolAddress((void**)&st2S, g_st2S);
    cudaGetSymbolAddress((void**)&st2Q, g_st2Q);
    cudaGetSymbolAddress((void**)&stHS, g_stHS);
    cudaGetSymbolAddress((void**)&stHQ, g_stHQ);
    cudaGetSymbolAddress((void**)&bnAh, g_bnAh);
    cudaGetSymbolAddress((void**)&bnBh, g_bnBh);
    cudaGetSymbolAddress((void**)&bnA1, g_bnA1);
    cudaGetSymbolAddress((void**)&bnB1, g_bnB1);
    cudaGetSymbolAddress((void**)&bnA2, g_bnA2);
    cudaGetSymbolAddress((void**)&bnB2, g_bnB2);
    cudaGetSymbolAddress((void**)&hg, g_hg);
    cudaGetSymbolAddress((void**)&cnt, g_cnt);

    // setup: atom encoder + CSR by destination (edge structure constant across layers)
    atom_kernel<<<NN, 128>>>(x, atom_emb, hA);
    cudaMemsetAsync(deg, 0, NN * sizeof(int));
    hist_kernel<<<(NE + 255) / 256, 256>>>(dst, deg);
    scan_kernel<<<1, 1024>>>(deg, rowptr, cursor);
    scatter_kernel<<<(NE + 255) / 256, 256>>>(dst, cursor, eids);

    float* hcur = hA;
    float* hnxt = hB;
    const int MBLK = (NN + 127) / 128;  // 782
    dim3 gridH(HH / 64, MBLK);
    dim3 gridD(DD / 64, MBLK);

    for (int l = 0; l < NL; l++) {
        // pre-layer BN affine (uses stats accumulated by previous layer's GEMM3) + zero st1
        finalize_kernel<<<1, 256>>>(l ? stHS : nullptr, stHQ,
                                    l ? norm_g + (size_t)(l - 1) * DD : nullptr,
                                    l ? norm_b + (size_t)(l - 1) * DD : nullptr,
                                    bnAh, bnBh, DD, st1S, st1Q, HH);
        agg_kernel<<<NN / 8, 256>>>(hcur, l ? bnAh : nullptr, l ? bnBh : nullptr,
                                    src, eattr, rowptr, eids,
                                    bond_emb + (size_t)l * 3 * 6 * DD, tt, l, hh);
        gemm_kernel<<<gridH, 256>>>(hh, W1 + (size_t)l * DD * HH, b1 + (size_t)l * HH,
                                    nullptr, nullptr, nullptr, y1, st1S, st1Q, DD, HH);
        finalize_kernel<<<1, 256>>>(st1S, st1Q, g1 + (size_t)l * HH, be1 + (size_t)l * HH,
                                    bnA1, bnB1, HH, st2S, st2Q, HH);
        gemm_kernel<<<gridH, 256>>>(y1, W2 + (size_t)l * HH * HH, b2 + (size_t)l * HH,
                                    bnA1, bnB1, nullptr, y2, st2S, st2Q, HH, HH);
        finalize_kernel<<<1, 256>>>(st2S, st2Q, g2 + (size_t)l * HH, be2 + (size_t)l * HH,
                                    bnA2, bnB2, HH, stHS, stHQ, DD);
        gemm_kernel<<<gridD, 256>>>(y2, W3 + (size_t)l * HH * DD, b3 + (size_t)l * DD,
                                    bnA2, bnB2, l ? hcur : nullptr, hnxt, stHS, stHQ, HH, DD);
        float* tmp = hcur; hcur = hnxt; hnxt = tmp;
    }
    // final BN + mean pool + prediction head
    finalize_kernel<<<1, 256>>>(stHS, stHQ, norm_g + (size_t)(NL - 1) * DD,
                                norm_b + (size_t)(NL - 1) * DD, bnAh, bnBh, DD,
                                nullptr, nullptr, 0);
    cudaMemsetAsync(hg, 0, (size_t)NG * DD * sizeof(float));
    cudaMemsetAsync(cnt, 0, NG * sizeof(float));
    pool_kernel<<<NN, 128>>>(hcur, bnAh, bnBh, batch, hg, cnt);
    out_kernel<<<NG, 128>>>(hg, cnt, predW, predb, out);
}

// round 5
// speedup vs baseline: 1.1980x; 1.1980x over previous
#include <cuda_runtime.h>
#include <cuda_bf16.h>
#include <cstdint>

#define NN 100000
#define NE 400000
#define NG 4096
#define DD 128
#define HH 256
#define NL 20
#define G_EPS 1e-7f
#define BNEPS 1e-5f

// ---------------- scratch (static device memory; no allocation) ----------------
__device__ float g_hA[(size_t)NN * DD];
__device__ float g_hB[(size_t)NN * DD];
__device__ float g_hh[(size_t)NN * DD];
__device__ float g_y1[(size_t)NN * HH];
__device__ float g_y2[(size_t)NN * HH];
__device__ int   g_deg[NN];
__device__ int   g_rowptr[NN + 1];
__device__ int   g_cursor[NN];
__device__ int   g_eids[NE];
__device__ float g_st1S[HH], g_st1Q[HH];
__device__ float g_st2S[HH], g_st2Q[HH];
__device__ float g_stHS[DD], g_stHQ[DD];
__device__ float g_bnAh[DD], g_bnBh[DD];
__device__ float g_bnA1[HH], g_bnB1[HH];
__device__ float g_bnA2[HH], g_bnB2[HH];
__device__ float g_hg[(size_t)NG * DD];
__device__ float g_cnt[NG];
// pre-split transposed weights: [L][N][K] bf16 hi/lo
__device__ __align__(16) __nv_bfloat16 g_w1hi[(size_t)NL * HH * DD];
__device__ __align__(16) __nv_bfloat16 g_w1lo[(size_t)NL * HH * DD];
__device__ __align__(16) __nv_bfloat16 g_w2hi[(size_t)NL * HH * HH];
__device__ __align__(16) __nv_bfloat16 g_w2lo[(size_t)NL * HH * HH];
__device__ __align__(16) __nv_bfloat16 g_w3hi[(size_t)NL * DD * HH];
__device__ __align__(16) __nv_bfloat16 g_w3lo[(size_t)NL * DD * HH];

// ================= helpers =================
static __device__ __forceinline__ uint32_t pack_bf16(float a, float b) {
    __nv_bfloat162 v = __floats2bfloat162_rn(a, b);
    return *reinterpret_cast<uint32_t*>(&v);
}

// mma.sync bf16 m16n8k16 row.col (sm_80+; valid on plain sm_103 target)
static __device__ __forceinline__ void mma16816(float* c, const uint32_t* a,
                                                uint32_t b0, uint32_t b1) {
    asm volatile(
        "mma.sync.aligned.m16n8k16.row.col.f32.bf16.bf16.f32 "
        "{%0,%1,%2,%3}, {%4,%5,%6,%7}, {%8,%9}, {%0,%1,%2,%3};"
        : "+f"(c[0]), "+f"(c[1]), "+f"(c[2]), "+f"(c[3])
        : "r"(a[0]), "r"(a[1]), "r"(a[2]), "r"(a[3]), "r"(b0), "r"(b1));
}

// ---------------- atom encoder ----------------
__global__ void atom_kernel(const int* __restrict__ x, const float* __restrict__ emb,
                            float* __restrict__ h) {
    int n = blockIdx.x, c = threadIdx.x;
    __shared__ int xi[9];
    if (c < 9) xi[c] = x[n * 9 + c];
    __syncthreads();
    float s = 0.f;
#pragma unroll
    for (int i = 0; i < 9; i++) s += emb[((size_t)i * 119 + xi[i]) * DD + c];
    h[(size_t)n * DD + c] = s;
}

// ---------------- CSR build ----------------
__global__ void hist_kernel(const int* __restrict__ dst, int* __restrict__ deg) {
    int e = blockIdx.x * blockDim.x + threadIdx.x;
    if (e < NE) atomicAdd(&deg[dst[e]], 1);
}

__global__ void scan_kernel(const int* __restrict__ deg, int* __restrict__ rowptr,
                            int* __restrict__ cursor) {
    __shared__ int sums[1024];
    int tid = threadIdx.x;
    const int CH = (NN + 1023) / 1024;
    int start = tid * CH;
    int s = 0;
    for (int i = 0; i < CH; i++) {
        int idx = start + i;
        if (idx < NN) s += deg[idx];
    }
    sums[tid] = s;
    __syncthreads();
    for (int off = 1; off < 1024; off <<= 1) {
        int v = (tid >= off) ? sums[tid - off] : 0;
        __syncthreads();
        sums[tid] += v;
        __syncthreads();
    }
    int run = (tid == 0) ? 0 : sums[tid - 1];
    for (int i = 0; i < CH; i++) {
        int idx = start + i;
        if (idx < NN) {
            rowptr[idx] = run;
            cursor[idx] = run;
            run += deg[idx];
        }
    }
    if (tid == 1023) rowptr[NN] = sums[1023];
}

__global__ void scatter_kernel(const int* __restrict__ dst, int* __restrict__ cursor,
                               int* __restrict__ eids) {
    int e = blockIdx.x * blockDim.x + threadIdx.x;
    if (e < NE) {
        int pos = atomicAdd(&cursor[dst[e]], 1);
        eids[pos] = e;
    }
}

// ---------------- GENConv aggregation (one warp per node, online softmax) ----------------
__global__ __launch_bounds__(256) void agg_kernel(
    const float* __restrict__ h, const float* __restrict__ bnA, const float* __restrict__ bnB,
    const int* __restrict__ src, const int* __restrict__ eattr,
    const int* __restrict__ rowptr, const int* __restrict__ eids,
    const float* __restrict__ bond, const float* __restrict__ tptr, int layer,
    float* __restrict__ hh) {
    __shared__ float sb[3 * 6 * DD];
    int tid = threadIdx.x;
    for (int i = tid; i < 3 * 6 * DD; i += blockDim.x) sb[i] = bond[i];
    __syncthreads();
    float t = __ldg(&tptr[layer]);
    int warp = blockIdx.x * (blockDim.x >> 5) + (tid >> 5);
    if (warp >= NN) return;
    int lane = tid & 31;
    bool hasBn = (bnA != nullptr);

    float A[4], B[4], h2n[4];
#pragma unroll
    for (int u = 0; u < 4; u++) {
        int c = lane + 32 * u;
        float a = hasBn ? bnA[c] : 1.f;
        float b = hasBn ? bnB[c] : 0.f;
        A[u] = a; B[u] = b;
        float v = h[(size_t)warp * DD + c];
        if (hasBn) v = fmaxf(v * a + b, 0.f);
        h2n[u] = v;
    }
    const float NEGINF = __int_as_float(0xff800000);
    float m[4] = {NEGINF, NEGINF, NEGINF, NEGINF};
    float s1[4] = {0.f, 0.f, 0.f, 0.f};
    float s2[4] = {0.f, 0.f, 0.f, 0.f};
    int e0 = rowptr[warp], e1 = rowptr[warp + 1];
    for (int e = e0; e < e1; e++) {
        int eid = eids[e];
        int s = src[eid];
        int a0 = eattr[eid * 3 + 0];
        int a1 = eattr[eid * 3 + 1];
        int a2 = eattr[eid * 3 + 2];
        const float* hs = h + (size_t)s * DD;
#pragma unroll
        for (int u = 0; u < 4; u++) {
            int c = lane + 32 * u;
            float hv = hs[c];
            if (hasBn) hv = fmaxf(hv * A[u] + B[u], 0.f);
            float ee = sb[a0 * DD + c] + sb[(6 + a1) * DD + c] + sb[(12 + a2) * DD + c];
            float msg = fmaxf(hv + ee, 0.f) + G_EPS;
            float sc = msg * t;
            if (sc > m[u]) {
                float r = __expf(m[u] - sc);
                s1[u] = s1[u] * r + 1.f;
                s2[u] = s2[u] * r + msg;
                m[u] = sc;
            } else {
                float ex = __expf(sc - m[u]);
                s1[u] += ex;
                s2[u] += msg * ex;
            }
        }
    }
#pragma unroll
    for (int u = 0; u < 4; u++) {
        float mm = s2[u] / fmaxf(s1[u], G_EPS);
        hh[(size_t)warp * DD + lane + 32 * u] = h2n[u] + mm;
    }
}

// ---------------- weight pre-transpose + bf16 hi/lo split: [L][K][N] -> [L][N][K] ------------
__global__ void splitw_kernel(const float* __restrict__ W, int K, int N, int total,
                              __nv_bfloat16* __restrict__ hiT, __nv_bfloat16* __restrict__ loT) {
    int i = blockIdx.x * blockDim.x + threadIdx.x;
    if (i >= total) return;
    int n = i % N;
    int k = (i / N) % K;
    int l = i / (N * K);
    float w = W[i];
    __nv_bfloat16 hi = __float2bfloat16_rn(w);
    float lo = w - __bfloat162float(hi);
    size_t o = ((size_t)l * N + n) * K + k;
    hiT[o] = hi;
    loT[o] = __float2bfloat16_rn(lo);
}

// ---------------- bf16-split mma.sync GEMM ----------------
// C[M,N] = f(A)[M,K] @ BT^T + bias (+res); f(a) = trA ? relu(a*trA[k]+trB[k]) : a.
// BT is [N][K] bf16 hi/lo pre-split. Column sum/sumsq stats fused into epilogue.
// CTA tile 128x64; 8 warps (4 m x 2 n), warp tile 32x32; K chunk 32.
// SMEM rows padded to 20 u32 (80B) -> conflict-free fragment loads.
template <int K, int N>
__global__ __launch_bounds__(256) void mgemm_kernel(
    const float* __restrict__ A, const __nv_bfloat16* __restrict__ BThi,
    const __nv_bfloat16* __restrict__ BTlo, const float* __restrict__ bias,
    const float* __restrict__ trA, const float* __restrict__ trB,
    const float* __restrict__ res, float* __restrict__ C,
    float* __restrict__ statS, float* __restrict__ statQ) {
    __shared__ uint32_t sAhi[128 * 20];
    __shared__ uint32_t sAlo[128 * 20];
    __shared__ uint32_t sBhi[64 * 20];
    __shared__ uint32_t sBlo[64 * 20];
    __shared__ float biasSm[64];
    __shared__ float trASm[256], trBSm[256];

    const int t = threadIdx.x;
    const int warp = t >> 5, lane = t & 31;
    const int gc0 = blockIdx.x * 64;
    const int growBase = blockIdx.y * 128;
    const bool hasTr = (trA != nullptr);

    if (t < 64) biasSm[t] = bias[gc0 + t];
    if (hasTr) {
        for (int i = t; i < K; i += 256) { trASm[i] = trA[i]; trBSm[i] = trB[i]; }
    }

    const int arow = t >> 1;
    const int aseg = t & 1;          // which 16-float half of the 32-k chunk
    const int grow = growBase + arow;
    const bool rowValid = (grow < NN);
    const float* arp = A + (size_t)grow * K;

    float acc[2][4][4];
#pragma unroll
    for (int mi = 0; mi < 2; mi++)
#pragma unroll
        for (int nj = 0; nj < 4; nj++)
#pragma unroll
            for (int q = 0; q < 4; q++) acc[mi][nj][q] = 0.f;

    __syncthreads();

    constexpr int NCH = K / 32;
    for (int ch = 0; ch < NCH; ch++) {
        const int k0 = ch * 32;
        // ---- stage A: fp32 load, transform, split, STS ----
        {
            float av[16];
            if (rowValid) {
#pragma unroll
                for (int g = 0; g < 4; g++) {
                    float4 v = *(const float4*)(arp + k0 + aseg * 16 + g * 4);
                    av[g * 4 + 0] = v.x; av[g * 4 + 1] = v.y;
                    av[g * 4 + 2] = v.z; av[g * 4 + 3] = v.w;
                }
                if (hasTr) {
#pragma unroll
                    for (int j = 0; j < 16; j++) {
                        int kg = k0 + aseg * 16 + j;
                        av[j] = fmaxf(av[j] * trASm[kg] + trBSm[kg], 0.f);
                    }
                }
            } else {
#pragma unroll
                for (int j = 0; j < 16; j++) av[j] = 0.f;
            }
            uint32_t hp[8], lp[8];
#pragma unroll
            for (int p = 0; p < 8; p++) {
                float a0 = av[2 * p], a1 = av[2 * p + 1];
                float h0 = __bfloat162float(__float2bfloat16_rn(a0));
                float h1 = __bfloat162float(__float2bfloat16_rn(a1));
                hp[p] = pack_bf16(h0, h1);
                lp[p] = pack_bf16(a0 - h0, a1 - h1);
            }
            uint32_t* pH = &sAhi[arow * 20 + aseg * 8];
            uint32_t* pL = &sAlo[arow * 20 + aseg * 8];
            *(uint4*)pH = make_uint4(hp[0], hp[1], hp[2], hp[3]);
            *(uint4*)(pH + 4) = make_uint4(hp[4], hp[5], hp[6], hp[7]);
            *(uint4*)pL = make_uint4(lp[0], lp[1], lp[2], lp[3]);
            *(uint4*)(pL + 4) = make_uint4(lp[4], lp[5], lp[6], lp[7]);
        }
        // ---- stage B: pre-split bf16 copy ----
        if (t < 128) {
            int brow = t >> 1;
            int seg = t & 1;
            const uint4* gh = (const uint4*)(BThi + (size_t)(gc0 + brow) * K + k0 + seg * 16);
            const uint4* gl = (const uint4*)(BTlo + (size_t)(gc0 + brow) * K + k0 + seg * 16);
            uint4 h0 = gh[0], h1 = gh[1];
            uint4 l0 = gl[0], l1 = gl[1];
            uint32_t* pH = &sBhi[brow * 20 + seg * 8];
            uint32_t* pL = &sBlo[brow * 20 + seg * 8];
            *(uint4*)pH = h0; *(uint4*)(pH + 4) = h1;
            *(uint4*)pL = l0; *(uint4*)(pL + 4) = l1;
        }
        __syncthreads();
        // ---- mma: 2 k-steps of 16, 3 split passes ----
#pragma unroll
        for (int ks = 0; ks < 2; ks++) {
            uint32_t ah[2][4], al[2][4];
#pragma unroll
            for (int mi = 0; mi < 2; mi++) {
                int rb = (warp >> 1) * 32 + mi * 16 + (lane >> 2);
                int idx = rb * 20 + ks * 8 + (lane & 3);
                ah[mi][0] = sAhi[idx];       ah[mi][1] = sAhi[idx + 160];
                ah[mi][2] = sAhi[idx + 4];   ah[mi][3] = sAhi[idx + 164];
                al[mi][0] = sAlo[idx];       al[mi][1] = sAlo[idx + 160];
                al[mi][2] = sAlo[idx + 4];   al[mi][3] = sAlo[idx + 164];
            }
#pragma unroll
            for (int nj = 0; nj < 4; nj++) {
                int nb = (warp & 1) * 32 + nj * 8 + (lane >> 2);
                int bidx = nb * 20 + ks * 8 + (lane & 3);
                uint32_t bh0 = sBhi[bidx], bh1 = sBhi[bidx + 4];
                uint32_t bl0 = sBlo[bidx], bl1 = sBlo[bidx + 4];
#pragma unroll
                for (int mi = 0; mi < 2; mi++) {
                    mma16816(acc[mi][nj], ah[mi], bh0, bh1);
                    mma16816(acc[mi][nj], ah[mi], bl0, bl1);
                    mma16816(acc[mi][nj], al[mi], bh0, bh1);
                }
            }
        }
        __syncthreads();
    }

    // ---- epilogue: bias (+res) store + column stats ----
    const bool doStat = (statS != nullptr);
#pragma unroll
    for (int nj = 0; nj < 4; nj++) {
        int cnl = (warp & 1) * 32 + nj * 8 + (lane & 3) * 2;
        int cn = gc0 + cnl;
        float b0 = biasSm[cnl], b1 = biasSm[cnl + 1];
        float se = 0.f, qe = 0.f, so = 0.f, qo = 0.f;
#pragma unroll
        for (int mi = 0; mi < 2; mi++) {
            int rA = growBase + (warp >> 1) * 32 + mi * 16 + (lane >> 2);
            int rB = rA + 8;
            bool mA = (rA < NN), mB = (rB < NN);
            float v0 = acc[mi][nj][0] + b0;
            float v1 = acc[mi][nj][1] + b1;
            float v2 = acc[mi][nj][2] + b0;
            float v3 = acc[mi][nj][3] + b1;
            if (res != nullptr) {
                if (mA) {
                    float2 rv = *(const float2*)(res + (size_t)rA * N + cn);
                    v0 += rv.x; v1 += rv.y;
                }
                if (mB) {
                    float2 rv = *(const float2*)(res + (size_t)rB * N + cn);
                    v2 += rv.x; v3 += rv.y;
                }
            }
            if (mA) *(float2*)(C + (size_t)rA * N + cn) = make_float2(v0, v1);
            if (mB) *(float2*)(C + (size_t)rB * N + cn) = make_float2(v2, v3);
            if (doStat) {
                if (mA) { se += v0; qe += v0 * v0; so += v1; qo += v1 * v1; }
                if (mB) { se += v2; qe += v2 * v2; so += v3; qo += v3 * v3; }
            }
        }
        if (doStat) {
#pragma unroll
            for (int off = 4; off < 32; off <<= 1) {
                se += __shfl_xor_sync(0xffffffffu, se, off);
                qe += __shfl_xor_sync(0xffffffffu, qe, off);
                so += __shfl_xor_sync(0xffffffffu, so, off);
                qo += __shfl_xor_sync(0xffffffffu, qo, off);
            }
            if (lane < 4) {
                atomicAdd(&statS[cn], se);
                atomicAdd(&statQ[cn], qe);
                atomicAdd(&statS[cn + 1], so);
                atomicAdd(&statQ[cn + 1], qo);
            }
        }
    }
}

// ---------------- BN stat finalize (+ zero next-stage stat buffers) ----------------
__global__ void finalize_kernel(const float* __restrict__ sum, const float* __restrict__ sq,
                                const float* __restrict__ g, const float* __restrict__ be,
                                float* __restrict__ outA, float* __restrict__ outB, int C,
                                float* __restrict__ z1, float* __restrict__ z2, int zlen) {
    int i = threadIdx.x;
    if (sum != nullptr && i < C) {
        float mu = sum[i] * (1.f / NN);
        float var = sq[i] * (1.f / NN) - mu * mu;
        float inv = rsqrtf(var + BNEPS);
        float a = g[i] * inv;
        outA[i] = a;
        outB[i] = be[i] - mu * a;
    }
    if (z1 != nullptr) {
        for (int j = i; j < zlen; j += blockDim.x) { z1[j] = 0.f; z2[j] = 0.f; }
    }
}

// ---------------- final BN + graph mean pool ----------------
__global__ void pool_kernel(const float* __restrict__ h, const float* __restrict__ bnA,
                            const float* __restrict__ bnB, const int* __restrict__ batch,
                            float* __restrict__ hg, float* __restrict__ cnt) {
    int n = blockIdx.x, c = threadIdx.x;
    int b = batch[n];
    float v = h[(size_t)n * DD + c] * bnA[c] + bnB[c];
    atomicAdd(&hg[(size_t)b * DD + c], v);
    if (c == 0) atomicAdd(&cnt[b], 1.f);
}

__global__ void out_kernel(const float* __restrict__ hg, const float* __restrict__ cnt,
                           const float* __restrict__ predW, const float* __restrict__ predb,
                           float* __restrict__ out) {
    int g = blockIdx.x, c = threadIdx.x;
    float scale = 1.f / fmaxf(cnt[g], 1.f);
    float v = hg[(size_t)g * DD + c] * scale * predW[c];
#pragma unroll
    for (int off = 16; off; off >>= 1) v += __shfl_down_sync(0xffffffffu, v, off);
    __shared__ float ws[4];
    if ((c & 31) == 0) ws[c >> 5] = v;
    __syncthreads();
    if (c == 0) out[g] = ws[0] + ws[1] + ws[2] + ws[3] + predb[0];
}

// ---------------- host orchestration ----------------
extern "C" void kernel_launch(void* const* d_in, const int* in_sizes, int n_in,
                              void* d_out, int out_size) {
    const int*   x        = (const int*)d_in[0];
    const int*   eidx     = (const int*)d_in[1];
    const int*   eattr    = (const int*)d_in[2];
    const int*   batch    = (const int*)d_in[3];
    const float* atom_emb = (const float*)d_in[4];
    const float* bond_emb = (const float*)d_in[5];
    const float* W1 = (const float*)d_in[6];
    const float* b1 = (const float*)d_in[7];
    const float* g1 = (const float*)d_in[8];
    const float* be1 = (const float*)d_in[9];
    const float* W2 = (const float*)d_in[10];
    const float* b2 = (const float*)d_in[11];
    const float* g2 = (const float*)d_in[12];
    const float* be2 = (const float*)d_in[13];
    const float* W3 = (const float*)d_in[14];
    const float* b3 = (const float*)d_in[15];
    const float* tt = (const float*)d_in[16];
    const float* norm_g = (const float*)d_in[17];
    const float* norm_b = (const float*)d_in[18];
    const float* predW = (const float*)d_in[19];
    const float* predb = (const float*)d_in[20];
    float* out = (float*)d_out;

    const int* src = eidx;
    const int* dst = eidx + NE;

    float *hA, *hB, *hh, *y1, *y2;
    int *deg, *rowptr, *cursor, *eids;
    float *st1S, *st1Q, *st2S, *st2Q, *stHS, *stHQ;
    float *bnAh, *bnBh, *bnA1, *bnB1, *bnA2, *bnB2;
    float *hg, *cnt;
    __nv_bfloat16 *w1hi, *w1lo, *w2hi, *w2lo, *w3hi, *w3lo;
    cudaGetSymbolAddress((void**)&hA, g_hA);
    cudaGetSymbolAddress((void**)&hB, g_hB);
    cudaGetSymbolAddress((void**)&hh, g_hh);
    cudaGetSymbolAddress((void**)&y1, g_y1);
    cudaGetSymbolAddress((void**)&y2, g_y2);
    cudaGetSymbolAddress((void**)&deg, g_deg);
    cudaGetSymbolAddress((void**)&rowptr, g_rowptr);
    cudaGetSymbolAddress((void**)&cursor, g_cursor);
    cudaGetSymbolAddress((void**)&eids, g_eids);
    cudaGetSymbolAddress((void**)&st1S, g_st1S);
    cudaGetSymbolAddress((void**)&st1Q, g_st1Q);
    cudaGetSymbolAddress((void**)&st2S, g_st2S);
    cudaGetSymbolAddress((void**)&st2Q, g_st2Q);
    cudaGetSymbolAddress((void**)&stHS, g_stHS);
    cudaGetSymbolAddress((void**)&stHQ, g_stHQ);
    cudaGetSymbolAddress((void**)&bnAh, g_bnAh);
    cudaGetSymbolAddress((void**)&bnBh, g_bnBh);
    cudaGetSymbolAddress((void**)&bnA1, g_bnA1);
    cudaGetSymbolAddress((void**)&bnB1, g_bnB1);
    cudaGetSymbolAddress((void**)&bnA2, g_bnA2);
    cudaGetSymbolAddress((void**)&bnB2, g_bnB2);
    cudaGetSymbolAddress((void**)&hg, g_hg);
    cudaGetSymbolAddress((void**)&cnt, g_cnt);
    cudaGetSymbolAddress((void**)&w1hi, g_w1hi);
    cudaGetSymbolAddress((void**)&w1lo, g_w1lo);
    cudaGetSymbolAddress((void**)&w2hi, g_w2hi);
    cudaGetSymbolAddress((void**)&w2lo, g_w2lo);
    cudaGetSymbolAddress((void**)&w3hi, g_w3hi);
    cudaGetSymbolAddress((void**)&w3lo, g_w3lo);

    // setup: atom encoder + CSR + weight pre-split
    atom_kernel<<<NN, 128>>>(x, atom_emb, hA);
    cudaMemsetAsync(deg, 0, NN * sizeof(int));
    hist_kernel<<<(NE + 255) / 256, 256>>>(dst, deg);
    scan_kernel<<<1, 1024>>>(deg, rowptr, cursor);
    scatter_kernel<<<(NE + 255) / 256, 256>>>(dst, cursor, eids);
    {
        int t1 = NL * DD * HH;
        splitw_kernel<<<(t1 + 255) / 256, 256>>>(W1, DD, HH, t1, w1hi, w1lo);
        int t2 = NL * HH * HH;
        splitw_kernel<<<(t2 + 255) / 256, 256>>>(W2, HH, HH, t2, w2hi, w2lo);
        int t3 = NL * HH * DD;
        splitw_kernel<<<(t3 + 255) / 256, 256>>>(W3, HH, DD, t3, w3hi, w3lo);
    }

    float* hcur = hA;
    float* hnxt = hB;
    const int MBLK = (NN + 127) / 128;  // 782
    dim3 gridH(HH / 64, MBLK);
    dim3 gridD(DD / 64, MBLK);

    for (int l = 0; l < NL; l++) {
        finalize_kernel<<<1, 256>>>(l ? stHS : nullptr, stHQ,
                                    l ? norm_g + (size_t)(l - 1) * DD : nullptr,
                                    l ? norm_b + (size_t)(l - 1) * DD : nullptr,
                                    bnAh, bnBh, DD, st1S, st1Q, HH);
        agg_kernel<<<NN / 8, 256>>>(hcur, l ? bnAh : nullptr, l ? bnBh : nullptr,
                                    src, eattr, rowptr, eids,
                                    bond_emb + (size_t)l * 3 * 6 * DD, tt, l, hh);
        mgemm_kernel<DD, HH><<<gridH, 256>>>(
            hh, w1hi + (size_t)l * HH * DD, w1lo + (size_t)l * HH * DD, b1 + (size_t)l * HH,
            nullptr, nullptr, nullptr, y1, st1S, st1Q);
        finalize_kernel<<<1, 256>>>(st1S, st1Q, g1 + (size_t)l * HH, be1 + (size_t)l * HH,
                                    bnA1, bnB1, HH, st2S, st2Q, HH);
        mgemm_kernel<HH, HH><<<gridH, 256>>>(
            y1, w2hi + (size_t)l * HH * HH, w2lo + (size_t)l * HH * HH, b2 + (size_t)l * HH,
            bnA1, bnB1, nullptr, y2, st2S, st2Q);
        finalize_kernel<<<1, 256>>>(st2S, st2Q, g2 + (size_t)l * HH, be2 + (size_t)l * HH,
                                    bnA2, bnB2, HH, stHS, stHQ, DD);
        mgemm_kernel<HH, DD><<<gridD, 256>>>(
            y2, w3hi + (size_t)l * DD * HH, w3lo + (size_t)l * DD * HH, b3 + (size_t)l * DD,
            bnA2, bnB2, l ? hcur : nullptr, hnxt, stHS, stHQ);
        float* tmp = hcur; hcur = hnxt; hnxt = tmp;
    }
    finalize_kernel<<<1, 256>>>(stHS, stHQ, norm_g + (size_t)(NL - 1) * DD,
                                norm_b + (size_t)(NL - 1) * DD, bnAh, bnBh, DD,
                                nullptr, nullptr, 0);
    cudaMemsetAsync(hg, 0, (size_t)NG * DD * sizeof(float));
    cudaMemsetAsync(cnt, 0, NG * sizeof(float));
    pool_kernel<<<NN, 128>>>(hcur, bnAh, bnBh, batch, hg, cnt);
    out_kernel<<<NG, 128>>>(hg, cnt, predW, predb, out);
}

// round 7
// speedup vs baseline: 1.3622x; 1.1370x over previous
#include <cuda_runtime.h>
#include <cuda_bf16.h>
#include <cstdint>

#define NN 100000
#define NE 400000
#define NG 4096
#define DD 128
#define HH 256
#define NL 20
#define G_EPS 1e-7f
#define BNEPS 1e-5f

// ---------------- scratch (static device memory; no allocation) ----------------
__device__ float g_hA[(size_t)NN * DD];
__device__ float g_hB[(size_t)NN * DD];
__device__ float g_hh[(size_t)NN * DD];
__device__ float g_y1[(size_t)NN * HH];
__device__ float g_y2[(size_t)NN * HH];
__device__ int   g_deg[NN];
__device__ int   g_rowptr[NN + 1];
__device__ int   g_cursor[NN];
__device__ int   g_eids[NE];
__device__ float g_st1S[HH], g_st1Q[HH];
__device__ float g_st2S[HH], g_st2Q[HH];
__device__ float g_stHS[DD], g_stHQ[DD];
__device__ float g_bnAh[DD], g_bnBh[DD];
__device__ float g_bnA1[HH], g_bnB1[HH];
__device__ float g_bnA2[HH], g_bnB2[HH];
__device__ float g_hg[(size_t)NG * DD];
__device__ float g_cnt[NG];
// pre-split transposed weights: [L][N][K] bf16 hi/lo
__device__ __align__(16) __nv_bfloat16 g_w1hi[(size_t)NL * HH * DD];
__device__ __align__(16) __nv_bfloat16 g_w1lo[(size_t)NL * HH * DD];
__device__ __align__(16) __nv_bfloat16 g_w2hi[(size_t)NL * HH * HH];
__device__ __align__(16) __nv_bfloat16 g_w2lo[(size_t)NL * HH * HH];
__device__ __align__(16) __nv_bfloat16 g_w3hi[(size_t)NL * DD * HH];
__device__ __align__(16) __nv_bfloat16 g_w3lo[(size_t)NL * DD * HH];

// ================= helpers =================
static __device__ __forceinline__ uint32_t pack_bf16(float a, float b) {
    __nv_bfloat162 v = __floats2bfloat162_rn(a, b);
    return *reinterpret_cast<uint32_t*>(&v);
}

static __device__ __forceinline__ void mma16816(float* c, const uint32_t* a,
                                                uint32_t b0, uint32_t b1) {
    asm volatile(
        "mma.sync.aligned.m16n8k16.row.col.f32.bf16.bf16.f32 "
        "{%0,%1,%2,%3}, {%4,%5,%6,%7}, {%8,%9}, {%0,%1,%2,%3};"
        : "+f"(c[0]), "+f"(c[1]), "+f"(c[2]), "+f"(c[3])
        : "r"(a[0]), "r"(a[1]), "r"(a[2]), "r"(a[3]), "r"(b0), "r"(b1));
}

static __device__ __forceinline__ void ldsm_x4(uint32_t* r, uint32_t saddr) {
    asm volatile("ldmatrix.sync.aligned.m8n8.x4.shared.b16 {%0,%1,%2,%3}, [%4];"
                 : "=r"(r[0]), "=r"(r[1]), "=r"(r[2]), "=r"(r[3]) : "r"(saddr));
}

#define CP_ASYNC16(sm, gp) \
    asm volatile("cp.async.cg.shared.global [%0], [%1], 16;" :: "r"(sm), "l"(gp))
#define CP_COMMIT() asm volatile("cp.async.commit_group;" ::: "memory")
#define CP_WAIT0() asm volatile("cp.async.wait_group 0;" ::: "memory")

// ---------------- atom encoder ----------------
__global__ void atom_kernel(const int* __restrict__ x, const float* __restrict__ emb,
                            float* __restrict__ h) {
    int n = blockIdx.x, c = threadIdx.x;
    __shared__ int xi[9];
    if (c < 9) xi[c] = x[n * 9 + c];
    __syncthreads();
    float s = 0.f;
#pragma unroll
    for (int i = 0; i < 9; i++) s += emb[((size_t)i * 119 + xi[i]) * DD + c];
    h[(size_t)n * DD + c] = s;
}

// ---------------- CSR build ----------------
__global__ void hist_kernel(const int* __restrict__ dst, int* __restrict__ deg) {
    int e = blockIdx.x * blockDim.x + threadIdx.x;
    if (e < NE) atomicAdd(&deg[dst[e]], 1);
}

__global__ void scan_kernel(const int* __restrict__ deg, int* __restrict__ rowptr,
                            int* __restrict__ cursor) {
    __shared__ int sums[1024];
    int tid = threadIdx.x;
    const int CH = (NN + 1023) / 1024;
    int start = tid * CH;
    int s = 0;
    for (int i = 0; i < CH; i++) {
        int idx = start + i;
        if (idx < NN) s += deg[idx];
    }
    sums[tid] = s;
    __syncthreads();
    for (int off = 1; off < 1024; off <<= 1) {
        int v = (tid >= off) ? sums[tid - off] : 0;
        __syncthreads();
        sums[tid] += v;
        __syncthreads();
    }
    int run = (tid == 0) ? 0 : sums[tid - 1];
    for (int i = 0; i < CH; i++) {
        int idx = start + i;
        if (idx < NN) {
            rowptr[idx] = run;
            cursor[idx] = run;
            run += deg[idx];
        }
    }
    if (tid == 1023) rowptr[NN] = sums[1023];
}

__global__ void scatter_kernel(const int* __restrict__ dst, int* __restrict__ cursor,
                               int* __restrict__ eids) {
    int e = blockIdx.x * blockDim.x + threadIdx.x;
    if (e < NE) {
        int pos = atomicAdd(&cursor[dst[e]], 1);
        eids[pos] = e;
    }
}

// ---------------- GENConv aggregation (one warp per node, online softmax) ----------------
__global__ __launch_bounds__(256) void agg_kernel(
    const float* __restrict__ h, const float* __restrict__ bnA, const float* __restrict__ bnB,
    const int* __restrict__ src, const int* __restrict__ eattr,
    const int* __restrict__ rowptr, const int* __restrict__ eids,
    const float* __restrict__ bond, const float* __restrict__ tptr, int layer,
    float* __restrict__ hh) {
    __shared__ float sb[3 * 6 * DD];
    int tid = threadIdx.x;
    for (int i = tid; i < 3 * 6 * DD; i += blockDim.x) sb[i] = bond[i];
    __syncthreads();
    float t = __ldg(&tptr[layer]);
    int warp = blockIdx.x * (blockDim.x >> 5) + (tid >> 5);
    if (warp >= NN) return;
    int lane = tid & 31;
    bool hasBn = (bnA != nullptr);

    float A[4], B[4], h2n[4];
#pragma unroll
    for (int u = 0; u < 4; u++) {
        int c = lane + 32 * u;
        float a = hasBn ? bnA[c] : 1.f;
        float b = hasBn ? bnB[c] : 0.f;
        A[u] = a; B[u] = b;
        float v = h[(size_t)warp * DD + c];
        if (hasBn) v = fmaxf(v * a + b, 0.f);
        h2n[u] = v;
    }
    const float NEGINF = __int_as_float(0xff800000);
    float m[4] = {NEGINF, NEGINF, NEGINF, NEGINF};
    float s1[4] = {0.f, 0.f, 0.f, 0.f};
    float s2[4] = {0.f, 0.f, 0.f, 0.f};
    int e0 = rowptr[warp], e1 = rowptr[warp + 1];
    for (int e = e0; e < e1; e++) {
        int eid = eids[e];
        int s = src[eid];
        int a0 = eattr[eid * 3 + 0];
        int a1 = eattr[eid * 3 + 1];
        int a2 = eattr[eid * 3 + 2];
        const float* hs = h + (size_t)s * DD;
#pragma unroll
        for (int u = 0; u < 4; u++) {
            int c = lane + 32 * u;
            float hv = hs[c];
            if (hasBn) hv = fmaxf(hv * A[u] + B[u], 0.f);
            float ee = sb[a0 * DD + c] + sb[(6 + a1) * DD + c] + sb[(12 + a2) * DD + c];
            float msg = fmaxf(hv + ee, 0.f) + G_EPS;
            float sc = msg * t;
            if (sc > m[u]) {
                float r = __expf(m[u] - sc);
                s1[u] = s1[u] * r + 1.f;
                s2[u] = s2[u] * r + msg;
                m[u] = sc;
            } else {
                float ex = __expf(sc - m[u]);
                s1[u] += ex;
                s2[u] += msg * ex;
            }
        }
    }
#pragma unroll
    for (int u = 0; u < 4; u++) {
        float mm = s2[u] / fmaxf(s1[u], G_EPS);
        hh[(size_t)warp * DD + lane + 32 * u] = h2n[u] + mm;
    }
}

// ---------------- weight pre-transpose + bf16 hi/lo split: [L][K][N] -> [L][N][K] ------------
__global__ void splitw_kernel(const float* __restrict__ W, int K, int N, int total,
                              __nv_bfloat16* __restrict__ hiT, __nv_bfloat16* __restrict__ loT) {
    int i = blockIdx.x * blockDim.x + threadIdx.x;
    if (i >= total) return;
    int n = i % N;
    int k = (i / N) % K;
    int l = i / (N * K);
    float w = W[i];
    __nv_bfloat16 hi = __float2bfloat16_rn(w);
    float lo = w - __bfloat162float(hi);
    size_t o = ((size_t)l * N + n) * K + k;
    hiT[o] = hi;
    loT[o] = __float2bfloat16_rn(lo);
}

// ---------------- pipelined bf16-split mma.sync GEMM ----------------
// C[M,N] = f(A)[M,K] @ BT^T + bias (+res); f(a) = trA ? relu(a*trA[k]+trB[k]) : a.
// CTA tile 128x64; 8 warps (4m x 2n), warp tile 32x32; K chunk 32.
// A: single SMEM buffer, register-prefetch pipeline. B: cp.async double buffer.
// Fragments loaded via ldmatrix.x4 (conflict-free with 20-u32 row stride).
template <int K, int N>
__global__ __launch_bounds__(256, 2) void mgemm_kernel(
    const float* __restrict__ A, const __nv_bfloat16* __restrict__ BThi,
    const __nv_bfloat16* __restrict__ BTlo, const float* __restrict__ bias,
    const float* __restrict__ trA, const float* __restrict__ trB,
    const float* __restrict__ res, float* __restrict__ C,
    float* __restrict__ statS, float* __restrict__ statQ) {
    __shared__ uint32_t sAhi[128 * 20];
    __shared__ uint32_t sAlo[128 * 20];
    __shared__ uint32_t sBhi[2][64 * 20];
    __shared__ uint32_t sBlo[2][64 * 20];
    __shared__ float biasSm[64];
    __shared__ float trASm[256], trBSm[256];

    const int t = threadIdx.x;
    const int warp = t >> 5, lane = t & 31;
    const int warpM = warp >> 1, warpN = warp & 1;
    const int gc0 = blockIdx.x * 64;
    const int growBase = blockIdx.y * 128;
    const bool hasTr = (trA != nullptr);

    if (t < 64) biasSm[t] = bias[gc0 + t];
    if (hasTr) {
        for (int i = t; i < K; i += 256) { trASm[i] = trA[i]; trBSm[i] = trB[i]; }
    }
    __syncthreads();  // trASm/trBSm/biasSm visible before ANY staging reads them

    const int arow = t >> 1;
    const int aseg = t & 1;
    const int grow = growBase + arow;
    const bool rowValid = (grow < NN);
    const float* arp = A + (size_t)grow * K;

    const uint32_t sAhiB = (uint32_t)__cvta_generic_to_shared(sAhi);
    const uint32_t sAloB = (uint32_t)__cvta_generic_to_shared(sAlo);
    const uint32_t sBhiB = (uint32_t)__cvta_generic_to_shared(sBhi);
    const uint32_t sBloB = (uint32_t)__cvta_generic_to_shared(sBlo);

    // ldmatrix per-lane offsets (u32 units)
    const int aLOff = (warpM * 32 + (lane & 7) + ((lane >> 3) & 1) * 8) * 20 + (lane >> 4) * 4;
    const int bLOff = (warpN * 32 + (lane & 7) + (lane >> 4) * 8) * 20 + ((lane >> 3) & 1) * 4;

    // B cp.async mapping: thread t stages row t>>2, 16B quad t&3 (hi and lo)
    const int bRow = t >> 2, bQuad = t & 3;
    const size_t bGoff = (size_t)(gc0 + bRow) * K + bQuad * 8;
    const uint32_t bSoff = (uint32_t)(bRow * 20 + bQuad * 4) * 4;

    float acc[2][4][4];
#pragma unroll
    for (int mi = 0; mi < 2; mi++)
#pragma unroll
        for (int nj = 0; nj < 4; nj++)
#pragma unroll
            for (int q = 0; q < 4; q++) acc[mi][nj][q] = 0.f;

    // ---- A stage helper (LDG + transform into regs) ----
    auto ldgA = [&](int k0, float* av) {
        if (rowValid) {
#pragma unroll
            for (int g = 0; g < 4; g++) {
                float4 v = *(const float4*)(arp + k0 + aseg * 16 + g * 4);
                av[g * 4 + 0] = v.x; av[g * 4 + 1] = v.y;
                av[g * 4 + 2] = v.z; av[g * 4 + 3] = v.w;
            }
            if (hasTr) {
#pragma unroll
                for (int j = 0; j < 16; j++) {
                    int kg = k0 + aseg * 16 + j;
                    av[j] = fmaxf(av[j] * trASm[kg] + trBSm[kg], 0.f);
                }
            }
        } else {
#pragma unroll
            for (int j = 0; j < 16; j++) av[j] = 0.f;
        }
    };
    auto stsA = [&](const float* av) {
        uint32_t hp[8], lp[8];
#pragma unroll
        for (int p = 0; p < 8; p++) {
            float a0 = av[2 * p], a1 = av[2 * p + 1];
            float h0 = __bfloat162float(__float2bfloat16_rn(a0));
            float h1 = __bfloat162float(__float2bfloat16_rn(a1));
            hp[p] = pack_bf16(h0, h1);
            lp[p] = pack_bf16(a0 - h0, a1 - h1);
        }
        uint32_t* pH = &sAhi[arow * 20 + aseg * 8];
        uint32_t* pL = &sAlo[arow * 20 + aseg * 8];
        *(uint4*)pH = make_uint4(hp[0], hp[1], hp[2], hp[3]);
        *(uint4*)(pH + 4) = make_uint4(hp[4], hp[5], hp[6], hp[7]);
        *(uint4*)pL = make_uint4(lp[0], lp[1], lp[2], lp[3]);
        *(uint4*)(pL + 4) = make_uint4(lp[4], lp[5], lp[6], lp[7]);
    };
    auto cpB = [&](int buf, int k0) {
        CP_ASYNC16(sBhiB + (uint32_t)buf * 5120 + bSoff, (const void*)(BThi + bGoff + k0));
        CP_ASYNC16(sBloB + (uint32_t)buf * 5120 + bSoff, (const void*)(BTlo + bGoff + k0));
    };

    // ---- prologue: chunk 0 ----
    cpB(0, 0);
    CP_COMMIT();
    {
        float av[16];
        ldgA(0, av);
        stsA(av);
    }
    CP_WAIT0();
    __syncthreads();

    constexpr int NCH = K / 32;
    for (int ch = 0; ch < NCH; ch++) {
        const int cur = ch & 1;
        const bool more = (ch + 1 < NCH);
        float av[16];
        if (more) {
            cpB(cur ^ 1, (ch + 1) * 32);
            CP_COMMIT();
            ldgA((ch + 1) * 32, av);
        }
        // ---- mma on current chunk ----
        const uint32_t bhBase = sBhiB + (uint32_t)cur * 5120;
        const uint32_t blBase = sBloB + (uint32_t)cur * 5120;
#pragma unroll
        for (int ks = 0; ks < 2; ks++) {
            uint32_t ah[2][4], al[2][4];
#pragma unroll
            for (int mi = 0; mi < 2; mi++) {
                uint32_t off = (uint32_t)(aLOff + mi * 16 * 20 + ks * 8) * 4;
                ldsm_x4(ah[mi], sAhiB + off);
                ldsm_x4(al[mi], sAloB + off);
            }
#pragma unroll
            for (int njp = 0; njp < 2; njp++) {
                uint32_t bo = (uint32_t)(bLOff + njp * 16 * 20 + ks * 8) * 4;
                uint32_t bh[4], bl[4];
                ldsm_x4(bh, bhBase + bo);
                ldsm_x4(bl, blBase + bo);
#pragma unroll
                for (int mi = 0; mi < 2; mi++) {
                    mma16816(acc[mi][njp * 2], ah[mi], bh[0], bh[1]);
                    mma16816(acc[mi][njp * 2], ah[mi], bl[0], bl[1]);
                    mma16816(acc[mi][njp * 2], al[mi], bh[0], bh[1]);
                    mma16816(acc[mi][njp * 2 + 1], ah[mi], bh[2], bh[3]);
                    mma16816(acc[mi][njp * 2 + 1], ah[mi], bl[2], bl[3]);
                    mma16816(acc[mi][njp * 2 + 1], al[mi], bh[2], bh[3]);
                }
            }
        }
        __syncthreads();  // all reads of sA done
        if (more) {
            stsA(av);
            CP_WAIT0();
        }
        __syncthreads();  // sA / sB[next] staged
    }

    // ---- epilogue: bias (+res) store + column stats ----
    const bool doStat = (statS != nullptr);
#pragma unroll
    for (int njp = 0; njp < 2; njp++)
#pragma unroll
        for (int j = 0; j < 2; j++) {
            int nj = njp * 2 + j;
            int cnl = warpN * 32 + njp * 16 + j * 8 + (lane & 3) * 2;
            int cn = gc0 + cnl;
            float b0 = biasSm[cnl], b1 = biasSm[cnl + 1];
            float se = 0.f, qe = 0.f, so = 0.f, qo = 0.f;
#pragma unroll
            for (int mi = 0; mi < 2; mi++) {
                int rA = growBase + warpM * 32 + mi * 16 + (lane >> 2);
                int rB = rA + 8;
                bool mA = (rA < NN), mB = (rB < NN);
                float v0 = acc[mi][nj][0] + b0;
                float v1 = acc[mi][nj][1] + b1;
                float v2 = acc[mi][nj][2] + b0;
                float v3 = acc[mi][nj][3] + b1;
                if (res != nullptr) {
                    if (mA) {
                        float2 rv = *(const float2*)(res + (size_t)rA * N + cn);
                        v0 += rv.x; v1 += rv.y;
                    }
                    if (mB) {
                        float2 rv = *(const float2*)(res + (size_t)rB * N + cn);
                        v2 += rv.x; v3 += rv.y;
                    }
                }
                if (mA) *(float2*)(C + (size_t)rA * N + cn) = make_float2(v0, v1);
                if (mB) *(float2*)(C + (size_t)rB * N + cn) = make_float2(v2, v3);
                if (doStat) {
                    if (mA) { se += v0; qe += v0 * v0; so += v1; qo += v1 * v1; }
                    if (mB) { se += v2; qe += v2 * v2; so += v3; qo += v3 * v3; }
                }
            }
            if (doStat) {
#pragma unroll
                for (int off = 4; off < 32; off <<= 1) {
                    se += __shfl_xor_sync(0xffffffffu, se, off);
                    qe += __shfl_xor_sync(0xffffffffu, qe, off);
                    so += __shfl_xor_sync(0xffffffffu, so, off);
                    qo += __shfl_xor_sync(0xffffffffu, qo, off);
                }
                if (lane < 4) {
                    atomicAdd(&statS[cn], se);
                    atomicAdd(&statQ[cn], qe);
                    atomicAdd(&statS[cn + 1], so);
                    atomicAdd(&statQ[cn + 1], qo);
                }
            }
        }
}

// ---------------- BN stat finalize (+ zero next-stage stat buffers) ----------------
__global__ void finalize_kernel(const float* __restrict__ sum, const float* __restrict__ sq,
                                const float* __restrict__ g, const float* __restrict__ be,
                                float* __restrict__ outA, float* __restrict__ outB, int C,
                                float* __restrict__ z1, float* __restrict__ z2, int zlen) {
    int i = threadIdx.x;
    if (sum != nullptr && i < C) {
        float mu = sum[i] * (1.f / NN);
        float var = sq[i] * (1.f / NN) - mu * mu;
        float inv = rsqrtf(var + BNEPS);
        float a = g[i] * inv;
        outA[i] = a;
        outB[i] = be[i] - mu * a;
    }
    if (z1 != nullptr) {
        for (int j = i; j < zlen; j += blockDim.x) { z1[j] = 0.f; z2[j] = 0.f; }
    }
}

// ---------------- final BN + graph mean pool ----------------
__global__ void pool_kernel(const float* __restrict__ h, const float* __restrict__ bnA,
                            const float* __restrict__ bnB, const int* __restrict__ batch,
                            float* __restrict__ hg, float* __restrict__ cnt) {
    int n = blockIdx.x, c = threadIdx.x;
    int b = batch[n];
    float v = h[(size_t)n * DD + c] * bnA[c] + bnB[c];
    atomicAdd(&hg[(size_t)b * DD + c], v);
    if (c == 0) atomicAdd(&cnt[b], 1.f);
}

__global__ void out_kernel(const float* __restrict__ hg, const float* __restrict__ cnt,
                           const float* __restrict__ predW, const float* __restrict__ predb,
                           float* __restrict__ out) {
    int g = blockIdx.x, c = threadIdx.x;
    float scale = 1.f / fmaxf(cnt[g], 1.f);
    float v = hg[(size_t)g * DD + c] * scale * predW[c];
#pragma unroll
    for (int off = 16; off; off >>= 1) v += __shfl_down_sync(0xffffffffu, v, off);
    __shared__ float ws[4];
    if ((c & 31) == 0) ws[c >> 5] = v;
    __syncthreads();
    if (c == 0) out[g] = ws[0] + ws[1] + ws[2] + ws[3] + predb[0];
}

// ---------------- host orchestration ----------------
extern "C" void kernel_launch(void* const* d_in, const int* in_sizes, int n_in,
                              void* d_out, int out_size) {
    const int*   x        = (const int*)d_in[0];
    const int*   eidx     = (const int*)d_in[1];
    const int*   eattr    = (const int*)d_in[2];
    const int*   batch    = (const int*)d_in[3];
    const float* atom_emb = (const float*)d_in[4];
    const float* bond_emb = (const float*)d_in[5];
    const float* W1 = (const float*)d_in[6];
    const float* b1 = (const float*)d_in[7];
    const float* g1 = (const float*)d_in[8];
    const float* be1 = (const float*)d_in[9];
    const float* W2 = (const float*)d_in[10];
    const float* b2 = (const float*)d_in[11];
    const float* g2 = (const float*)d_in[12];
    const float* be2 = (const float*)d_in[13];
    const float* W3 = (const float*)d_in[14];
    const float* b3 = (const float*)d_in[15];
    const float* tt = (const float*)d_in[16];
    const float* norm_g = (const float*)d_in[17];
    const float* norm_b = (const float*)d_in[18];
    const float* predW = (const float*)d_in[19];
    const float* predb = (const float*)d_in[20];
    float* out = (float*)d_out;

    const int* src = eidx;
    const int* dst = eidx + NE;

    float *hA, *hB, *hh, *y1, *y2;
    int *deg, *rowptr, *cursor, *eids;
    float *st1S, *st1Q, *st2S, *st2Q, *stHS, *stHQ;
    float *bnAh, *bnBh, *bnA1, *bnB1, *bnA2, *bnB2;
    float *hg, *cnt;
    __nv_bfloat16 *w1hi, *w1lo, *w2hi, *w2lo, *w3hi, *w3lo;
    cudaGetSymbolAddress((void**)&hA, g_hA);
    cudaGetSymbolAddress((void**)&hB, g_hB);
    cudaGetSymbolAddress((void**)&hh, g_hh);
    cudaGetSymbolAddress((void**)&y1, g_y1);
    cudaGetSymbolAddress((void**)&y2, g_y2);
    cudaGetSymbolAddress((void**)&deg, g_deg);
    cudaGetSymbolAddress((void**)&rowptr, g_rowptr);
    cudaGetSymbolAddress((void**)&cursor, g_cursor);
    cudaGetSymbolAddress((void**)&eids, g_eids);
    cudaGetSymbolAddress((void**)&st1S, g_st1S);
    cudaGetSymbolAddress((void**)&st1Q, g_st1Q);
    cudaGetSymbolAddress((void**)&st2S, g_st2S);
    cudaGetSymbolAddress((void**)&st2Q, g_st2Q);
    cudaGetSymbolAddress((void**)&stHS, g_stHS);
    cudaGetSymbolAddress((void**)&stHQ, g_stHQ);
    cudaGetSymbolAddress((void**)&bnAh, g_bnAh);
    cudaGetSymbolAddress((void**)&bnBh, g_bnBh);
    cudaGetSymbolAddress((void**)&bnA1, g_bnA1);
    cudaGetSymbolAddress((void**)&bnB1, g_bnB1);
    cudaGetSymbolAddress((void**)&bnA2, g_bnA2);
    cudaGetSymbolAddress((void**)&bnB2, g_bnB2);
    cudaGetSymbolAddress((void**)&hg, g_hg);
    cudaGetSymbolAddress((void**)&cnt, g_cnt);
    cudaGetSymbolAddress((void**)&w1hi, g_w1hi);
    cudaGetSymbolAddress((void**)&w1lo, g_w1lo);
    cudaGetSymbolAddress((void**)&w2hi, g_w2hi);
    cudaGetSymbolAddress((void**)&w2lo, g_w2lo);
    cudaGetSymbolAddress((void**)&w3hi, g_w3hi);
    cudaGetSymbolAddress((void**)&w3lo, g_w3lo);

    // setup: atom encoder + CSR + weight pre-split
    atom_kernel<<<NN, 128>>>(x, atom_emb, hA);
    cudaMemsetAsync(deg, 0, NN * sizeof(int));
    hist_kernel<<<(NE + 255) / 256, 256>>>(dst, deg);
    scan_kernel<<<1, 1024>>>(deg, rowptr, cursor);
    scatter_kernel<<<(NE + 255) / 256, 256>>>(dst, cursor, eids);
    {
        int t1 = NL * DD * HH;
        splitw_kernel<<<(t1 + 255) / 256, 256>>>(W1, DD, HH, t1, w1hi, w1lo);
        int t2 = NL * HH * HH;
        splitw_kernel<<<(t2 + 255) / 256, 256>>>(W2, HH, HH, t2, w2hi, w2lo);
        int t3 = NL * HH * DD;
        splitw_kernel<<<(t3 + 255) / 256, 256>>>(W3, HH, DD, t3, w3hi, w3lo);
    }

    float* hcur = hA;
    float* hnxt = hB;
    const int MBLK = (NN + 127) / 128;  // 782
    dim3 gridH(HH / 64, MBLK);
    dim3 gridD(DD / 64, MBLK);

    for (int l = 0; l < NL; l++) {
        finalize_kernel<<<1, 256>>>(l ? stHS : nullptr, stHQ,
                                    l ? norm_g + (size_t)(l - 1) * DD : nullptr,
                                    l ? norm_b + (size_t)(l - 1) * DD : nullptr,
                                    bnAh, bnBh, DD, st1S, st1Q, HH);
        agg_kernel<<<NN / 8, 256>>>(hcur, l ? bnAh : nullptr, l ? bnBh : nullptr,
                                    src, eattr, rowptr, eids,
                                    bond_emb + (size_t)l * 3 * 6 * DD, tt, l, hh);
        mgemm_kernel<DD, HH><<<gridH, 256>>>(
            hh, w1hi + (size_t)l * HH * DD, w1lo + (size_t)l * HH * DD, b1 + (size_t)l * HH,
            nullptr, nullptr, nullptr, y1, st1S, st1Q);
        finalize_kernel<<<1, 256>>>(st1S, st1Q, g1 + (size_t)l * HH, be1 + (size_t)l * HH,
                                    bnA1, bnB1, HH, st2S, st2Q, HH);
        mgemm_kernel<HH, HH><<<gridH, 256>>>(
            y1, w2hi + (size_t)l * HH * HH, w2lo + (size_t)l * HH * HH, b2 + (size_t)l * HH,
            bnA1, bnB1, nullptr, y2, st2S, st2Q);
        finalize_kernel<<<1, 256>>>(st2S, st2Q, g2 + (size_t)l * HH, be2 + (size_t)l * HH,
                                    bnA2, bnB2, HH, stHS, stHQ, DD);
        mgemm_kernel<HH, DD><<<gridD, 256>>>(
            y2, w3hi + (size_t)l * DD * HH, w3lo + (size_t)l * DD * HH, b3 + (size_t)l * DD,
            bnA2, bnB2, l ? hcur : nullptr, hnxt, stHS, stHQ);
        float* tmp = hcur; hcur = hnxt; hnxt = tmp;
    }
    finalize_kernel<<<1, 256>>>(stHS, stHQ, norm_g + (size_t)(NL - 1) * DD,
                                norm_b + (size_t)(NL - 1) * DD, bnAh, bnBh, DD,
                                nullptr, nullptr, 0);
    cudaMemsetAsync(hg, 0, (size_t)NG * DD * sizeof(float));
    cudaMemsetAsync(cnt, 0, NG * sizeof(float));
    pool_kernel<<<NN, 128>>>(hcur, bnAh, bnBh, batch, hg, cnt);
    out_kernel<<<NG, 128>>>(hg, cnt, predW, predb, out);
}